// round 2
// baseline (speedup 1.0000x reference)
#include <cuda_runtime.h>
#include <math.h>

#define TW 32
#define TH 8
#define NT 256
#define IMW 512
#define IMH 512
#define NCH 12
#define NBINS 256

// SMEM weight layout (per predictor), rows 16B-aligned for LDS.128:
//  w0:  32 rows of [24 taps weights, bias] stride 28
//  wA:  32 rows of [32 w1, b1] stride 36
//  wB:  32 rows of [32 w2, b2] stride 36
//  wC:  [32 w3, b3] (36)
#define W0_STRIDE 28
#define WA_OFF (32 * W0_STRIDE)              // 896
#define WAB_STRIDE 36
#define WB_OFF (WA_OFF + 32 * WAB_STRIDE)    // 2048
#define WC_OFF (WB_OFF + 32 * WAB_STRIDE)    // 3200
#define PRED_STRIDE (WC_OFF + 36)            // 3236 floats (x4B = 16B multiple)

struct Params { const float* p[27]; };

__device__ double g_sumsq[2];                    // [0]=x, [1]=delta
__device__ unsigned int g_hist[2][NCH][NBINS];   // [0]=x, [1]=delta

__global__ void zero_kernel() {
    int i = blockIdx.x * blockDim.x + threadIdx.x;
    if (i < 2) g_sumsq[i] = 0.0;
    if (i < 2 * NCH * NBINS) ((unsigned int*)g_hist)[i] = 0u;
}

__device__ __forceinline__ float leaky(float v) { return fmaxf(v, 0.01f * v); }

// ---- packed f32x2 primitives (sm_103a FFMA2 path; ptxas never emits these from C++) ----
typedef unsigned long long u64;

__device__ __forceinline__ u64 ffma2(u64 a, u64 b, u64 c) {
    u64 d;
    asm("fma.rn.f32x2 %0, %1, %2, %3;" : "=l"(d) : "l"(a), "l"(b), "l"(c));
    return d;
}
__device__ __forceinline__ u64 fadd2(u64 a, u64 b) {
    u64 d;
    asm("add.rn.f32x2 %0, %1, %2;" : "=l"(d) : "l"(a), "l"(b));
    return d;
}
__device__ __forceinline__ u64 pack2(float lo, float hi) {
    u64 r;
    asm("mov.b64 %0, {%1, %2};" : "=l"(r) : "f"(lo), "f"(hi));
    return r;
}
__device__ __forceinline__ float2 unpack2(u64 v) {
    float2 r;
    asm("mov.b64 {%0, %1}, %2;" : "=f"(r.x), "=f"(r.y) : "l"(v));
    return r;
}

__global__ __launch_bounds__(NT) void predict_kernel(const float* __restrict__ x, Params prm) {
    __shared__ float s_tile[TH + 3][TW + 8];                 // 11 x 38 used
    __shared__ __align__(16) float s_w[3 * PRED_STRIDE];     // ~38.8 KB
    __shared__ unsigned int s_hist[2][NBINS];
    __shared__ double s_red[2][NT / 32];

    const int tx = threadIdx.x, ty = threadIdx.y;
    const int tid = ty * TW + tx;
    const int ch  = blockIdx.z;
    const int gx0 = blockIdx.x * TW;
    const int gy0 = blockIdx.y * TH;

    // zero shared hist
    for (int i = tid; i < 2 * NBINS; i += NT) ((unsigned int*)s_hist)[i] = 0u;

    // stage weights into padded SMEM layout
    for (int p = 0; p < 3; ++p) {
        const float* wT = prm.p[p * 9 + 0];
        const float* bT = prm.p[p * 9 + 1];
        const float* wL = prm.p[p * 9 + 2];
        const float* w1 = prm.p[p * 9 + 3];
        const float* b1 = prm.p[p * 9 + 4];
        const float* w2 = prm.p[p * 9 + 5];
        const float* b2 = prm.p[p * 9 + 6];
        const float* w3 = prm.p[p * 9 + 7];
        const float* b3 = prm.p[p * 9 + 8];
        float* base = s_w + p * PRED_STRIDE;
        for (int i = tid; i < 32 * 21; i += NT) base[(i / 21) * W0_STRIDE + (i % 21)] = wT[i];
        for (int i = tid; i < 32 * 3;  i += NT) base[(i / 3) * W0_STRIDE + 21 + (i % 3)] = wL[i];
        for (int i = tid; i < 32;      i += NT) base[i * W0_STRIDE + 24] = bT[i];
        for (int i = tid; i < 32 * 32; i += NT) base[WA_OFF + (i / 32) * WAB_STRIDE + (i % 32)] = w1[i];
        for (int i = tid; i < 32;      i += NT) base[WA_OFF + i * WAB_STRIDE + 32] = b1[i];
        for (int i = tid; i < 32 * 32; i += NT) base[WB_OFF + (i / 32) * WAB_STRIDE + (i % 32)] = w2[i];
        for (int i = tid; i < 32;      i += NT) base[WB_OFF + i * WAB_STRIDE + 32] = b2[i];
        for (int i = tid; i < 32;      i += NT) base[WC_OFF + i] = w3[i];
        if (tid == 0) base[WC_OFF + 32] = b3[0];
    }

    // stage input tile with halo (top 3 rows, left 3 / right 3 cols), zero-padded
    const float* xch = x + (size_t)ch * IMH * IMW;
    for (int i = tid; i < (TH + 3) * (TW + 6); i += NT) {
        int r = i / (TW + 6), c = i % (TW + 6);
        int gr = gy0 - 3 + r, gc = gx0 - 3 + c;
        float v = 0.f;
        if (gr >= 0 && gc >= 0 && gc < IMW) v = xch[gr * IMW + gc];
        s_tile[r][c] = v;
    }
    __syncthreads();

    // gather 24 causal taps, packed in k-pairs:
    // taps: rows i-3..i-1 cols j-3..j+3 (21), then row i cols j-3..j-1 (3)
    float t[24];
#pragma unroll
    for (int di = 0; di < 3; ++di)
#pragma unroll
        for (int dj = 0; dj < 7; ++dj)
            t[di * 7 + dj] = s_tile[ty + di][tx + dj];
#pragma unroll
    for (int dj = 0; dj < 3; ++dj)
        t[21 + dj] = s_tile[ty + 3][tx + dj];

    u64 t2[12];
#pragma unroll
    for (int k = 0; k < 12; ++k) t2[k] = pack2(t[2 * k], t[2 * k + 1]);

    u64 ha[16], hb[16];   // packed activations (pairs of channels along k of next layer)
    float preds[3];

#pragma unroll 1
    for (int p = 0; p < 3; ++p) {
        const float* wb = s_w + p * PRED_STRIDE;

        // ---- layer 0: 24 taps -> 32 ch ----
#pragma unroll
        for (int ocp = 0; ocp < 16; ++ocp) {
            const float* w0 = wb + (2 * ocp) * W0_STRIDE;
            const float* w1 = w0 + W0_STRIDE;
            const ulonglong2* q0 = (const ulonglong2*)w0;
            const ulonglong2* q1 = (const ulonglong2*)w1;
            u64 a0 = 0ull, b0 = 0ull, a1 = 0ull, b1 = 0ull;
#pragma unroll
            for (int q = 0; q < 6; ++q) {
                ulonglong2 v0 = q0[q], v1 = q1[q];
                a0 = ffma2(v0.x, t2[2 * q], a0);
                b0 = ffma2(v0.y, t2[2 * q + 1], b0);
                a1 = ffma2(v1.x, t2[2 * q], a1);
                b1 = ffma2(v1.y, t2[2 * q + 1], b1);
            }
            float2 s0 = unpack2(fadd2(a0, b0));
            float2 s1 = unpack2(fadd2(a1, b1));
            float v0s = (s0.x + s0.y) + w0[24];
            float v1s = (s1.x + s1.y) + w1[24];
            ha[ocp] = pack2(leaky(v0s), leaky(v1s));
        }

        // ---- layer 1: 32 -> 32 ----
#pragma unroll
        for (int ocp = 0; ocp < 16; ++ocp) {
            const float* w0 = wb + WA_OFF + (2 * ocp) * WAB_STRIDE;
            const float* w1 = w0 + WAB_STRIDE;
            const ulonglong2* q0 = (const ulonglong2*)w0;
            const ulonglong2* q1 = (const ulonglong2*)w1;
            u64 a0 = 0ull, b0 = 0ull, a1 = 0ull, b1 = 0ull;
#pragma unroll
            for (int q = 0; q < 8; ++q) {
                ulonglong2 v0 = q0[q], v1 = q1[q];
                a0 = ffma2(v0.x, ha[2 * q], a0);
                b0 = ffma2(v0.y, ha[2 * q + 1], b0);
                a1 = ffma2(v1.x, ha[2 * q], a1);
                b1 = ffma2(v1.y, ha[2 * q + 1], b1);
            }
            float2 s0 = unpack2(fadd2(a0, b0));
            float2 s1 = unpack2(fadd2(a1, b1));
            float v0s = (s0.x + s0.y) + w0[32];
            float v1s = (s1.x + s1.y) + w1[32];
            hb[ocp] = pack2(leaky(v0s), leaky(v1s));
        }

        // ---- layer 2: 32 -> 32 ----
#pragma unroll
        for (int ocp = 0; ocp < 16; ++ocp) {
            const float* w0 = wb + WB_OFF + (2 * ocp) * WAB_STRIDE;
            const float* w1 = w0 + WAB_STRIDE;
            const ulonglong2* q0 = (const ulonglong2*)w0;
            const ulonglong2* q1 = (const ulonglong2*)w1;
            u64 a0 = 0ull, b0 = 0ull, a1 = 0ull, b1 = 0ull;
#pragma unroll
            for (int q = 0; q < 8; ++q) {
                ulonglong2 v0 = q0[q], v1 = q1[q];
                a0 = ffma2(v0.x, hb[2 * q], a0);
                b0 = ffma2(v0.y, hb[2 * q + 1], b0);
                a1 = ffma2(v1.x, hb[2 * q], a1);
                b1 = ffma2(v1.y, hb[2 * q + 1], b1);
            }
            float2 s0 = unpack2(fadd2(a0, b0));
            float2 s1 = unpack2(fadd2(a1, b1));
            float v0s = (s0.x + s0.y) + w0[32];
            float v1s = (s1.x + s1.y) + w1[32];
            ha[ocp] = pack2(leaky(v0s), leaky(v1s));   // reuse ha as h3
        }

        // ---- head: 32 -> 1 ----
        {
            const float* w = wb + WC_OFF;
            const ulonglong2* qw = (const ulonglong2*)w;
            u64 a0 = 0ull, b0 = 0ull;
#pragma unroll
            for (int q = 0; q < 8; ++q) {
                ulonglong2 v = qw[q];
                a0 = ffma2(v.x, ha[2 * q], a0);
                b0 = ffma2(v.y, ha[2 * q + 1], b0);
            }
            float2 s = unpack2(fadd2(a0, b0));
            float a = (s.x + s.y) + w[32];
            preds[p] = fminf(fmaxf(a, -1.f), 1.f);
        }
    }

    const float x0 = s_tile[ty + 3][tx + 3];
    const float pa = preds[0], pb = preds[1], pc = preds[2];
    const float med = fmaxf(fminf(pa, fmaxf(pb, pc)), fminf(pb, pc));
    const float delta = fmodf(x0 - med + 1.0f, 2.0f) - 1.0f;

    // per-channel histograms via shared atomics (mask: only values in [-1,1] counted)
    if (x0 >= -1.f && x0 <= 1.f) {
        int idx = (int)floorf((x0 + 1.f) * 128.f);
        idx = min(max(idx, 0), NBINS - 1);
        atomicAdd(&s_hist[0][idx], 1u);
    }
    if (delta >= -1.f && delta <= 1.f) {
        int idx = (int)floorf((delta + 1.f) * 128.f);
        idx = min(max(idx, 0), NBINS - 1);
        atomicAdd(&s_hist[1][idx], 1u);
    }

    // sum-of-squares block reduction (double)
    double vx = (double)x0 * (double)x0;
    double vd = (double)delta * (double)delta;
#pragma unroll
    for (int o = 16; o > 0; o >>= 1) {
        vx += __shfl_down_sync(0xffffffffu, vx, o);
        vd += __shfl_down_sync(0xffffffffu, vd, o);
    }
    const int warp = tid >> 5, lane = tid & 31;
    if (lane == 0) { s_red[0][warp] = vx; s_red[1][warp] = vd; }
    __syncthreads();
    if (tid == 0) {
        double sx = 0.0, sd = 0.0;
#pragma unroll
        for (int i = 0; i < NT / 32; ++i) { sx += s_red[0][i]; sd += s_red[1][i]; }
        atomicAdd(&g_sumsq[0], sx);
        atomicAdd(&g_sumsq[1], sd);
    }
    if (tid < NBINS) {
        unsigned c0 = s_hist[0][tid], c1 = s_hist[1][tid];
        if (c0) atomicAdd(&g_hist[0][ch][tid], c0);
        if (c1) atomicAdd(&g_hist[1][ch][tid], c1);
    }
}

__global__ void finalize_kernel(float* out) {
    __shared__ double s_ent[2][8];
    const int tid = threadIdx.x;
    double e0 = 0.0, e1 = 0.0;
    const double res = (double)(IMH * IMW);
    for (int i = tid; i < NCH * NBINS; i += 256) {
        unsigned c0 = ((const unsigned*)g_hist[0])[i];
        unsigned c1 = ((const unsigned*)g_hist[1])[i];
        if (c0) { double pp = (double)c0 / res; e0 -= pp * log2(pp); }
        if (c1) { double pp = (double)c1 / res; e1 -= pp * log2(pp); }
    }
#pragma unroll
    for (int o = 16; o > 0; o >>= 1) {
        e0 += __shfl_down_sync(0xffffffffu, e0, o);
        e1 += __shfl_down_sync(0xffffffffu, e1, o);
    }
    if ((tid & 31) == 0) { s_ent[0][tid >> 5] = e0; s_ent[1][tid >> 5] = e1; }
    __syncthreads();
    if (tid == 0) {
        double E0 = 0.0, E1 = 0.0;
#pragma unroll
        for (int i = 0; i < 8; ++i) { E0 += s_ent[0][i]; E1 += s_ent[1][i]; }
        const double N = (double)NCH * IMH * IMW;
        out[0] = (float)(255.0 * sqrt(g_sumsq[1] / N));   // loss1
        out[1] = (float)(255.0 * sqrt(g_sumsq[0] / N));   // loss0
        out[2] = (float)(E0 / (8.0 * NCH));               // invCR0
        out[3] = (float)(E1 / (8.0 * NCH));               // invCR1
    }
}

extern "C" void kernel_launch(void* const* d_in, const int* in_sizes, int n_in,
                              void* d_out, int out_size) {
    const float* x = (const float*)d_in[0];
    Params prm;
    for (int i = 0; i < 27; ++i) prm.p[i] = (const float*)d_in[1 + i];

    zero_kernel<<<24, 256>>>();
    dim3 grid(IMW / TW, IMH / TH, NCH);
    dim3 block(TW, TH);
    predict_kernel<<<grid, block>>>(x, prm);
    finalize_kernel<<<1, 256>>>((float*)d_out);
}

// round 4
// speedup vs baseline: 1.8102x; 1.8102x over previous
#include <cuda_runtime.h>
#include <cuda_fp16.h>
#include <math.h>
#include <cstdint>

#define NT 256
#define TILE_W 64
#define TILE_H 8
#define IMW 512
#define IMH 512
#define NCH 12
#define NBINS 256

struct Params { const float* p[27]; };

__device__ double g_sumsq[2];                    // [0]=x, [1]=delta
__device__ unsigned int g_hist[2][NCH][NBINS];   // [0]=x, [1]=delta

__global__ void zero_kernel() {
    int i = blockIdx.x * blockDim.x + threadIdx.x;
    if (i < 2) g_sumsq[i] = 0.0;
    if (i < 2 * NCH * NBINS) ((unsigned int*)g_hist)[i] = 0u;
}

__device__ __forceinline__ uint32_t h2u(__half2 h) { return *reinterpret_cast<uint32_t*>(&h); }
__device__ __forceinline__ __half2 u2h(uint32_t u) { return *reinterpret_cast<__half2*>(&u); }

// pack (m0.lo+m0.hi, m1.lo+m1.hi) as one half2 — 2 PRMT + 1 HADD2
__device__ __forceinline__ __half2 hpair_sum(__half2 m0, __half2 m1) {
    __half2 lo = u2h(__byte_perm(h2u(m0), h2u(m1), 0x5410));
    __half2 hi = u2h(__byte_perm(h2u(m0), h2u(m1), 0x7632));
    return __hadd2(lo, hi);
}

__global__ __launch_bounds__(NT) void predict_kernel(const float* __restrict__ x, Params prm) {
    // fp16x2 weights, K-pair packed, rows 16B-multiple strides for LDS.128
    __shared__ __align__(16) __half2 s_w0[3][32][12];      // layer0: 24 taps
    __shared__ __align__(16) __half2 s_w12[3][2][32][16];  // layers 1,2: 32 k
    __shared__ __align__(16) __half2 s_wh[3][16];          // head
    __shared__ __half2 s_bias[3][3][16];                   // channel-pair packed biases
    __shared__ float s_b3[3];
    __shared__ float s_tile[TILE_H + 3][TILE_W + 8];       // 11 x 70 used
    __shared__ unsigned int s_hist[2][NBINS];
    __shared__ double s_red[2][NT / 32];

    const int tx = threadIdx.x, ty = threadIdx.y;
    const int tid = ty * 32 + tx;
    const int ch  = blockIdx.z;
    const int gx0 = blockIdx.x * TILE_W;
    const int gy0 = blockIdx.y * TILE_H;

    for (int i = tid; i < 2 * NBINS; i += NT) ((unsigned int*)s_hist)[i] = 0u;

    // ---- stage weights fp32 -> fp16x2 ----
    for (int i = tid; i < 3 * 32 * 12; i += NT) {
        int p = i / 384, r = i % 384, oc = r / 12, q = r % 12;
        const float* wT = prm.p[p * 9 + 0];
        const float* wL = prm.p[p * 9 + 2];
        int k0 = 2 * q, k1 = 2 * q + 1;
        float f0 = (k0 < 21) ? wT[oc * 21 + k0] : wL[oc * 3 + (k0 - 21)];
        float f1 = (k1 < 21) ? wT[oc * 21 + k1] : wL[oc * 3 + (k1 - 21)];
        s_w0[p][oc][q] = __floats2half2_rn(f0, f1);
    }
    for (int i = tid; i < 3 * 2 * 32 * 16; i += NT) {
        int p = i / 1024, r = i % 1024, l = r / 512, r2 = r % 512, oc = r2 / 16, q = r2 % 16;
        const float* wm = prm.p[p * 9 + (l ? 5 : 3)];
        s_w12[p][l][oc][q] = __floats2half2_rn(wm[oc * 32 + 2 * q], wm[oc * 32 + 2 * q + 1]);
    }
    for (int i = tid; i < 3 * 16; i += NT) {
        int p = i / 16, q = i % 16;
        const float* w3 = prm.p[p * 9 + 7];
        s_wh[p][q] = __floats2half2_rn(w3[2 * q], w3[2 * q + 1]);
    }
    for (int i = tid; i < 3 * 3 * 16; i += NT) {
        int p = i / 48, r = i % 48, l = r / 16, q = r % 16;
        const float* b = prm.p[p * 9 + (l == 0 ? 1 : (l == 1 ? 4 : 6))];
        s_bias[p][l][q] = __floats2half2_rn(b[2 * q], b[2 * q + 1]);
    }
    if (tid < 3) s_b3[tid] = prm.p[tid * 9 + 8][0];

    // ---- stage input tile with halo ----
    const float* xch = x + (size_t)ch * IMH * IMW;
    for (int i = tid; i < (TILE_H + 3) * (TILE_W + 6); i += NT) {
        int r = i / (TILE_W + 6), c = i % (TILE_W + 6);
        int gr = gy0 - 3 + r, gc = gx0 - 3 + c;
        float v = 0.f;
        if (gr >= 0 && gc >= 0 && gc < IMW) v = xch[gr * IMW + gc];
        s_tile[r][c] = v;
    }
    __syncthreads();

    // ---- gather taps for 2 pixels (cols tx and tx+32), fp16x2 k-pairs ----
    __half2 t2[2][12];
#pragma unroll
    for (int px = 0; px < 2; ++px) {
        const int base = tx + px * 32;
        float tp[24];
#pragma unroll
        for (int di = 0; di < 3; ++di)
#pragma unroll
            for (int dj = 0; dj < 7; ++dj) tp[di * 7 + dj] = s_tile[ty + di][base + dj];
#pragma unroll
        for (int dj = 0; dj < 3; ++dj) tp[21 + dj] = s_tile[ty + 3][base + dj];
#pragma unroll
        for (int q = 0; q < 12; ++q) t2[px][q] = __floats2half2_rn(tp[2 * q], tp[2 * q + 1]);
    }

    const __half2 C001 = __float2half2_rn(0.01f);
    float preds[2][3];

#pragma unroll 1
    for (int p = 0; p < 3; ++p) {
        __half2 a1[2][16], a2[2][16];

        // ---- layer 0: 24 taps -> 32 ch ----
#pragma unroll
        for (int ocp = 0; ocp < 16; ++ocp) {
            const __half2* w0 = s_w0[p][2 * ocp];
            const __half2* w1 = s_w0[p][2 * ocp + 1];
#pragma unroll
            for (int px = 0; px < 2; ++px) {
                __half2 aA = __hmul2(w0[0], t2[px][0]);
                __half2 aB = __hmul2(w0[6], t2[px][6]);
                __half2 bA = __hmul2(w1[0], t2[px][0]);
                __half2 bB = __hmul2(w1[6], t2[px][6]);
#pragma unroll
                for (int q = 1; q < 6; ++q) {
                    aA = __hfma2(w0[q],     t2[px][q],     aA);
                    aB = __hfma2(w0[q + 6], t2[px][q + 6], aB);
                    bA = __hfma2(w1[q],     t2[px][q],     bA);
                    bB = __hfma2(w1[q + 6], t2[px][q + 6], bB);
                }
                __half2 s = __hadd2(hpair_sum(__hadd2(aA, aB), __hadd2(bA, bB)), s_bias[p][0][ocp]);
                a1[px][ocp] = __hmax2(s, __hmul2(s, C001));
            }
        }

        // ---- layer 1: 32 -> 32 ----
#pragma unroll
        for (int ocp = 0; ocp < 16; ++ocp) {
            const __half2* w0 = s_w12[p][0][2 * ocp];
            const __half2* w1 = s_w12[p][0][2 * ocp + 1];
#pragma unroll
            for (int px = 0; px < 2; ++px) {
                __half2 aA = __hmul2(w0[0], a1[px][0]);
                __half2 aB = __hmul2(w0[8], a1[px][8]);
                __half2 bA = __hmul2(w1[0], a1[px][0]);
                __half2 bB = __hmul2(w1[8], a1[px][8]);
#pragma unroll
                for (int q = 1; q < 8; ++q) {
                    aA = __hfma2(w0[q],     a1[px][q],     aA);
                    aB = __hfma2(w0[q + 8], a1[px][q + 8], aB);
                    bA = __hfma2(w1[q],     a1[px][q],     bA);
                    bB = __hfma2(w1[q + 8], a1[px][q + 8], bB);
                }
                __half2 s = __hadd2(hpair_sum(__hadd2(aA, aB), __hadd2(bA, bB)), s_bias[p][1][ocp]);
                a2[px][ocp] = __hmax2(s, __hmul2(s, C001));
            }
        }

        // ---- layer 2: 32 -> 32 ----
#pragma unroll
        for (int ocp = 0; ocp < 16; ++ocp) {
            const __half2* w0 = s_w12[p][1][2 * ocp];
            const __half2* w1 = s_w12[p][1][2 * ocp + 1];
#pragma unroll
            for (int px = 0; px < 2; ++px) {
                __half2 aA = __hmul2(w0[0], a2[px][0]);
                __half2 aB = __hmul2(w0[8], a2[px][8]);
                __half2 bA = __hmul2(w1[0], a2[px][0]);
                __half2 bB = __hmul2(w1[8], a2[px][8]);
#pragma unroll
                for (int q = 1; q < 8; ++q) {
                    aA = __hfma2(w0[q],     a2[px][q],     aA);
                    aB = __hfma2(w0[q + 8], a2[px][q + 8], aB);
                    bA = __hfma2(w1[q],     a2[px][q],     bA);
                    bB = __hfma2(w1[q + 8], a2[px][q + 8], bB);
                }
                __half2 s = __hadd2(hpair_sum(__hadd2(aA, aB), __hadd2(bA, bB)), s_bias[p][2][ocp]);
                a1[px][ocp] = __hmax2(s, __hmul2(s, C001));   // reuse a1 as h3
            }
        }

        // ---- head: 32 -> 1 (fp16 dot, fp32 bias/clip) ----
        const __half2* wh = s_wh[p];
#pragma unroll
        for (int px = 0; px < 2; ++px) {
            __half2 aA = __hmul2(wh[0], a1[px][0]);
            __half2 aB = __hmul2(wh[8], a1[px][8]);
#pragma unroll
            for (int q = 1; q < 8; ++q) {
                aA = __hfma2(wh[q],     a1[px][q],     aA);
                aB = __hfma2(wh[q + 8], a1[px][q + 8], aB);
            }
            __half2 m = __hadd2(aA, aB);
            float a = __low2float(m) + __high2float(m) + s_b3[p];
            preds[px][p] = fminf(fmaxf(a, -1.f), 1.f);
        }
    }

    // ---- stats for both pixels ----
    double acc_x = 0.0, acc_d = 0.0;
#pragma unroll
    for (int px = 0; px < 2; ++px) {
        const float x0 = s_tile[ty + 3][tx + px * 32 + 3];
        const float pa = preds[px][0], pb = preds[px][1], pc = preds[px][2];
        const float med = fmaxf(fminf(pa, fmaxf(pb, pc)), fminf(pb, pc));
        const float delta = fmodf(x0 - med + 1.0f, 2.0f) - 1.0f;

        if (x0 >= -1.f && x0 <= 1.f) {
            int idx = (int)floorf((x0 + 1.f) * 128.f);
            idx = min(max(idx, 0), NBINS - 1);
            atomicAdd(&s_hist[0][idx], 1u);
        }
        if (delta >= -1.f && delta <= 1.f) {
            int idx = (int)floorf((delta + 1.f) * 128.f);
            idx = min(max(idx, 0), NBINS - 1);
            atomicAdd(&s_hist[1][idx], 1u);
        }
        acc_x += (double)x0 * (double)x0;
        acc_d += (double)delta * (double)delta;
    }

    // ---- reductions ----
#pragma unroll
    for (int o = 16; o > 0; o >>= 1) {
        acc_x += __shfl_down_sync(0xffffffffu, acc_x, o);
        acc_d += __shfl_down_sync(0xffffffffu, acc_d, o);
    }
    const int warp = tid >> 5, lane = tid & 31;
    if (lane == 0) { s_red[0][warp] = acc_x; s_red[1][warp] = acc_d; }
    __syncthreads();
    if (tid == 0) {
        double sx = 0.0, sd = 0.0;
#pragma unroll
        for (int i = 0; i < NT / 32; ++i) { sx += s_red[0][i]; sd += s_red[1][i]; }
        atomicAdd(&g_sumsq[0], sx);
        atomicAdd(&g_sumsq[1], sd);
    }
    if (tid < NBINS) {
        unsigned c0 = s_hist[0][tid], c1 = s_hist[1][tid];
        if (c0) atomicAdd(&g_hist[0][ch][tid], c0);
        if (c1) atomicAdd(&g_hist[1][ch][tid], c1);
    }
}

__global__ void finalize_kernel(float* out) {
    __shared__ double s_ent[2][8];
    const int tid = threadIdx.x;
    double e0 = 0.0, e1 = 0.0;
    const double res = (double)(IMH * IMW);
    for (int i = tid; i < NCH * NBINS; i += 256) {
        unsigned c0 = ((const unsigned*)g_hist[0])[i];
        unsigned c1 = ((const unsigned*)g_hist[1])[i];
        if (c0) { double pp = (double)c0 / res; e0 -= pp * log2(pp); }
        if (c1) { double pp = (double)c1 / res; e1 -= pp * log2(pp); }
    }
#pragma unroll
    for (int o = 16; o > 0; o >>= 1) {
        e0 += __shfl_down_sync(0xffffffffu, e0, o);
        e1 += __shfl_down_sync(0xffffffffu, e1, o);
    }
    if ((tid & 31) == 0) { s_ent[0][tid >> 5] = e0; s_ent[1][tid >> 5] = e1; }
    __syncthreads();
    if (tid == 0) {
        double E0 = 0.0, E1 = 0.0;
#pragma unroll
        for (int i = 0; i < 8; ++i) { E0 += s_ent[0][i]; E1 += s_ent[1][i]; }
        const double N = (double)NCH * IMH * IMW;
        out[0] = (float)(255.0 * sqrt(g_sumsq[1] / N));   // loss1
        out[1] = (float)(255.0 * sqrt(g_sumsq[0] / N));   // loss0
        out[2] = (float)(E0 / (8.0 * NCH));               // invCR0
        out[3] = (float)(E1 / (8.0 * NCH));               // invCR1
    }
}

extern "C" void kernel_launch(void* const* d_in, const int* in_sizes, int n_in,
                              void* d_out, int out_size) {
    const float* x = (const float*)d_in[0];
    Params prm;
    for (int i = 0; i < 27; ++i) prm.p[i] = (const float*)d_in[1 + i];

    zero_kernel<<<24, 256>>>();
    dim3 grid(IMW / TILE_W, IMH / TILE_H, NCH);
    dim3 block(32, TILE_H);
    predict_kernel<<<grid, block>>>(x, prm);
    finalize_kernel<<<1, 256>>>((float*)d_out);
}